// round 1
// baseline (speedup 1.0000x reference)
#include <cuda_runtime.h>
#include <cuda_bf16.h>

// MultiScaleDeformableAttention, shapes fixed by the problem:
// B=2, nH=8, D=32, Q=21760, L=4 (128^2,64^2,32^2,16^2), P=4
// value:               (B, Len=21760, nH, D)   fp32
// sampling_locations:  (B, Q, nH, L, P, 2)     fp32
// attention_weights:   (B, Q, nH, L, P)        fp32
// out:                 (B, Q, nH*D)            fp32
//
// Mapping: one warp per (b,q,h); lane = channel d. Each corner read is one
// aligned contiguous 128B line (nH*D = 256 floats row stride, h*D*4 = 128B
// aligned sub-offset). value (44.6MB) fits in L2 -> L2-BW-bound kernel.

#define BB   2
#define NH   8
#define DD   32
#define QQ   21760
#define LEN  21760
#define ROWF (NH * DD)          // 256 floats per spatial location
#define NWARPS (BB * QQ * NH)   // 348160

__global__ __launch_bounds__(256)
void msda_kernel(const float* __restrict__ value,
                 const float* __restrict__ sloc,
                 const float* __restrict__ aw,
                 float* __restrict__ out)
{
    const int warp = (blockIdx.x * blockDim.x + threadIdx.x) >> 5;
    const int lane = threadIdx.x & 31;
    if (warp >= NWARPS) return;

    // warp = (b*Q + q)*nH + h
    const int h  = warp & (NH - 1);
    const int bq = warp >> 3;          // b*Q + q
    const int b  = bq / QQ;

    // Per-(b,q,h) sampling data: 32 contiguous loc floats, 16 contiguous weights.
    const float sval = sloc[(size_t)warp * 32 + lane];
    const float wval = (lane < 16) ? aw[(size_t)warp * 16 + lane] : 0.0f;

    // Channel-base pointer for this (b, h, lane)
    const float* __restrict__ vbase =
        value + (size_t)b * LEN * ROWF + h * DD + lane;

    float acc = 0.0f;

    const int   Hs[4]     = {128, 64, 32, 16};
    const int   starts[4] = {0, 16384, 20480, 21504};

    #pragma unroll
    for (int l = 0; l < 4; ++l) {
        const int   Hl = Hs[l];
        const int   Wl = Hl;
        const float fW = (float)Wl;
        const float fH = (float)Hl;
        const float* __restrict__ vl = vbase + (size_t)starts[l] * ROWF;

        #pragma unroll
        for (int p = 0; p < 4; ++p) {
            const int j = l * 4 + p;
            const float xl = __shfl_sync(0xffffffffu, sval, 2 * j);
            const float yl = __shfl_sync(0xffffffffu, sval, 2 * j + 1);
            const float w  = __shfl_sync(0xffffffffu, wval, j);

            // x = loc_x * W - 0.5 ; y = loc_y * H - 0.5
            const float x = fmaf(xl, fW, -0.5f);
            const float y = fmaf(yl, fH, -0.5f);

            const float x0f = floorf(x);
            const float y0f = floorf(y);
            const int   x0  = (int)x0f;
            const int   y0  = (int)y0f;
            const float lx  = x - x0f;
            const float ly  = y - y0f;
            const float hx  = 1.0f - lx;
            const float hy  = 1.0f - ly;

            const float w00 = w * hx * hy;   // (x0,   y0)
            const float w10 = w * lx * hy;   // (x0+1, y0)
            const float w01 = w * hx * ly;   // (x0,   y0+1)
            const float w11 = w * lx * ly;   // (x0+1, y0+1)

            const bool vx0 = (x0 >= 0)     & (x0 < Wl);
            const bool vx1 = (x0 >= -1)    & (x0 < Wl - 1);
            const bool vy0 = (y0 >= 0)     & (y0 < Hl);
            const bool vy1 = (y0 >= -1)    & (y0 < Hl - 1);

            // Row pointers (may point out of bounds when invalid; never
            // dereferenced in that case).
            const float* row0 = vl + (long long)(y0 * Wl) * ROWF;
            const float* row1 = row0 + (long long)Wl * ROWF;
            const long long cx0 = (long long)x0 * ROWF;
            const long long cx1 = cx0 + ROWF;

            if (vy0 & vx0) acc = fmaf(w00, __ldg(row0 + cx0), acc);
            if (vy0 & vx1) acc = fmaf(w10, __ldg(row0 + cx1), acc);
            if (vy1 & vx0) acc = fmaf(w01, __ldg(row1 + cx0), acc);
            if (vy1 & vx1) acc = fmaf(w11, __ldg(row1 + cx1), acc);
        }
    }

    // out[b, q, h*D + d] == out[warp*32 + lane]
    out[(size_t)warp * DD + lane] = acc;
}

extern "C" void kernel_launch(void* const* d_in, const int* in_sizes, int n_in,
                              void* d_out, int out_size)
{
    const float* value = (const float*)d_in[0];
    // d_in[1] = value_spatial_shapes (int64), d_in[2] = level_start (int64):
    // compile-time constants here.
    const float* sloc  = (const float*)d_in[3];
    const float* aw    = (const float*)d_in[4];
    float*       out   = (float*)d_out;

    const int threads = 256;                       // 8 warps/block
    const int blocks  = (NWARPS * 32 + threads - 1) / threads;  // 43520
    msda_kernel<<<blocks, threads>>>(value, sloc, aw, out);
}

// round 2
// speedup vs baseline: 2.2749x; 2.2749x over previous
#include <cuda_runtime.h>
#include <cuda_bf16.h>

// MultiScaleDeformableAttention, fixed shapes:
// B=2, nH=8, D=32, Q=21760, L=4 (128^2,64^2,32^2,16^2), P=4
// value: (B, Len, nH, D) fp32 ; sloc: (B,Q,nH,L,P,2) ; aw: (B,Q,nH,L,P)
// out:   (B, Q, nH*D) fp32
//
// R2 mapping: thread = float4 of channels; 8 lanes = 1 head; warp = 4 heads
// of one (b,q). Amortizes coord/address ALU 4x and uses LDG.128.

#define BB   2
#define NH   8
#define QQ   21760
#define LEN  21760
#define ROW4 64                  // 256 floats = 64 float4 per spatial location
#define NWARPS (BB * QQ * 2)     // 87040 (2 head-groups of 4)

__global__ __launch_bounds__(256)
void msda_kernel(const float4* __restrict__ value4,
                 const float4* __restrict__ sloc4,
                 const float2* __restrict__ aw2,
                 float4* __restrict__ out4)
{
    const int warp = (blockIdx.x * blockDim.x + threadIdx.x) >> 5;
    const int lane = threadIdx.x & 31;
    if (warp >= NWARPS) return;

    const int grp = lane >> 3;        // head within the 4-head group
    const int sub = lane & 7;         // channel-quad within head (4 ch)
    const int hg  = warp & 1;         // head group (0: heads 0-3, 1: 4-7)
    const int bq  = warp >> 1;        // b*Q + q
    const int b   = (bq >= QQ) ? 1 : 0;
    const int h   = hg * 4 + grp;
    const int whq = bq * NH + h;      // (b*Q+q)*8 + h

    // Per-(b,q,h) sampling data, spread over the 8 lanes of this head:
    // 32 loc floats -> 8 x float4 ; 16 weights -> 8 x float2.
    const float4 sv = __ldg(sloc4 + (size_t)whq * 8 + sub);
    const float2 wv = __ldg(aw2  + (size_t)whq * 8 + sub);

    // Base pointer for this (b, h, channel-quad), in float4 units.
    const float4* __restrict__ vb =
        value4 + (size_t)b * LEN * ROW4 + h * 8 + sub;

    float4 acc = make_float4(0.f, 0.f, 0.f, 0.f);

    const int Hs[4]     = {128, 64, 32, 16};
    const int starts[4] = {0, 16384, 20480, 21504};

    #pragma unroll
    for (int l = 0; l < 4; ++l) {
        const int   Wl = Hs[l];
        const int   Hl = Hs[l];
        const float fW = (float)Wl;
        const float fH = (float)Hl;
        const int   base = starts[l] * ROW4;   // float4 offset of level

        #pragma unroll
        for (int p = 0; p < 4; ++p) {
            const int j   = l * 4 + p;
            const int src = j >> 1;     // lane (within 8) holding sample j

            // sample j: loc floats 2j,2j+1 ; weight float j
            float xl, yl, w;
            if (j & 1) {
                xl = __shfl_sync(0xffffffffu, sv.z, src, 8);
                yl = __shfl_sync(0xffffffffu, sv.w, src, 8);
                w  = __shfl_sync(0xffffffffu, wv.y, src, 8);
            } else {
                xl = __shfl_sync(0xffffffffu, sv.x, src, 8);
                yl = __shfl_sync(0xffffffffu, sv.y, src, 8);
                w  = __shfl_sync(0xffffffffu, wv.x, src, 8);
            }

            // pixel coords: x = loc_x*W - 0.5
            const float x = fmaf(xl, fW, -0.5f);
            const float y = fmaf(yl, fH, -0.5f);

            const float x0f = floorf(x);
            const float y0f = floorf(y);
            const int   x0  = (int)x0f;
            const int   y0  = (int)y0f;
            const float lx  = x - x0f;
            const float ly  = y - y0f;
            const float hx  = 1.0f - lx;
            const float hy  = 1.0f - ly;

            // validity (zeros padding) + clamped coords for safe loads
            const bool vx0 = ((unsigned)x0       < (unsigned)Wl);
            const bool vx1 = ((unsigned)(x0 + 1) < (unsigned)Wl);
            const bool vy0 = ((unsigned)y0       < (unsigned)Hl);
            const bool vy1 = ((unsigned)(y0 + 1) < (unsigned)Hl);

            const float w00 = (vx0 & vy0) ? w * hx * hy : 0.f;
            const float w10 = (vx1 & vy0) ? w * lx * hy : 0.f;
            const float w01 = (vx0 & vy1) ? w * hx * ly : 0.f;
            const float w11 = (vx1 & vy1) ? w * lx * ly : 0.f;

            const int xc0 = min(max(x0,     0), Wl - 1);
            const int xc1 = min(max(x0 + 1, 0), Wl - 1);
            const int yc0 = min(max(y0,     0), Hl - 1);
            const int yc1 = min(max(y0 + 1, 0), Hl - 1);

            const int r0 = base + yc0 * (Wl * ROW4);
            const int r1 = base + yc1 * (Wl * ROW4);
            const int c0 = xc0 * ROW4;
            const int c1 = xc1 * ROW4;

            const float4 v00 = __ldg(vb + r0 + c0);
            const float4 v10 = __ldg(vb + r0 + c1);
            const float4 v01 = __ldg(vb + r1 + c0);
            const float4 v11 = __ldg(vb + r1 + c1);

            acc.x = fmaf(w00, v00.x, acc.x);
            acc.y = fmaf(w00, v00.y, acc.y);
            acc.z = fmaf(w00, v00.z, acc.z);
            acc.w = fmaf(w00, v00.w, acc.w);
            acc.x = fmaf(w10, v10.x, acc.x);
            acc.y = fmaf(w10, v10.y, acc.y);
            acc.z = fmaf(w10, v10.z, acc.z);
            acc.w = fmaf(w10, v10.w, acc.w);
            acc.x = fmaf(w01, v01.x, acc.x);
            acc.y = fmaf(w01, v01.y, acc.y);
            acc.z = fmaf(w01, v01.z, acc.z);
            acc.w = fmaf(w01, v01.w, acc.w);
            acc.x = fmaf(w11, v11.x, acc.x);
            acc.y = fmaf(w11, v11.y, acc.y);
            acc.z = fmaf(w11, v11.z, acc.z);
            acc.w = fmaf(w11, v11.w, acc.w);
        }
    }

    // out[b, q, h*32 + sub*4 .. +3]  ->  float4 index bq*64 + h*8 + sub
    out4[(size_t)bq * 64 + h * 8 + sub] = acc;
}

extern "C" void kernel_launch(void* const* d_in, const int* in_sizes, int n_in,
                              void* d_out, int out_size)
{
    const float4* value4 = (const float4*)d_in[0];
    // d_in[1] (shapes), d_in[2] (level starts): compile-time constants.
    const float4* sloc4  = (const float4*)d_in[3];
    const float2* aw2    = (const float2*)d_in[4];
    float4*       out4   = (float4*)d_out;

    const int threads = 256;                    // 8 warps/block
    const int blocks  = NWARPS / 8;             // 10880
    msda_kernel<<<blocks, threads>>>(value4, sloc4, aw2, out4);
}